// round 3
// baseline (speedup 1.0000x reference)
#include <cuda_runtime.h>
#include <math.h>

// ---------------- problem constants ----------------
// B=4, C=128, H=W=512, P=16, GH=GW=32, N=1024, PATCH_DIM=32768, DIM=512,
// MLP=256, DH=64, HEADS=(2,4,8), NUM_REL=3969

// ---------------- scratch (device globals; no allocation allowed) ----------
__device__ __align__(16) float g_pw2[32768 * 512];   // permuted patch_w (64 MB)
__device__ __align__(16) float g_x[4096 * 512];      // residual stream
__device__ __align__(16) float g_xn[4096 * 512];     // LN output
__device__ __align__(16) float g_qkv[4096 * 1536];   // qkv (max inner=512)
__device__ __align__(16) float g_attn[33554432];     // scores, B*8*N*N (128 MB)
__device__ __align__(16) float g_o[4096 * 512];      // attention output
__device__ __align__(16) float g_h[4096 * 256];      // FFN hidden

// scratch selector: all scratch addresses resolved ON DEVICE
#define BUF_X   0
#define BUF_XN  1
#define BUF_QKV 2
#define BUF_O   3
#define BUF_H   4
__device__ __forceinline__ float* buf(int id) {
    switch (id) {
        case BUF_X:   return g_x;
        case BUF_XN:  return g_xn;
        case BUF_QKV: return g_qkv;
        case BUF_O:   return g_o;
        default:      return g_h;
    }
}

// ============================================================================
__global__ void k_zero(float* o, int n) {
    int i = blockIdx.x * blockDim.x + threadIdx.x;
    if (i < n) o[i] = 0.0f;
}

// ============================================================================
// permute patch_w rows:  in row (p1*16+p2)*128 + c  ->  out row c*256 + p1*16+p2
// ============================================================================
__global__ void k_permute_pw(const float* __restrict__ pw) {
    int idx = blockIdx.x * blockDim.x + threadIdx.x;   // 32768 rows * 128 float4
    if (idx >= 32768 * 128) return;
    int r  = idx >> 7;
    int d4 = idx & 127;
    int p  = r >> 7;       // p1*16+p2
    int c  = r & 127;
    int rout = (c << 8) + p;
    float4 v = ((const float4*)pw)[(size_t)r * 128 + d4];
    ((float4*)g_pw2)[(size_t)rout * 128 + d4] = v;
}

// ============================================================================
// patch embed GEMM:  g_x[m][d] = sum_k' A[m][k'] * pw2[k'][d] + pb[d] + pos[n][d]
//   m = b*1024 + gh*32 + gw ;  k' = c*256 + p1*16 + p2
// ============================================================================
__global__ __launch_bounds__(256)
void k_patch_gemm(const float* __restrict__ img,
                  const float* __restrict__ pb,
                  const float* __restrict__ pos) {
    __shared__ __align__(16) float As[16][64];
    __shared__ __align__(16) float Bs[16][64];
    int tid = threadIdx.x;
    int m0 = blockIdx.y * 64;
    int n0 = blockIdx.x * 64;
    int arow = tid >> 2;
    int acol = (tid & 3) << 2;
    int brow = tid >> 4;
    int bcol = (tid & 15) << 2;
    int ty = tid >> 4, tx = tid & 15;

    int m  = m0 + arow;
    int bb = m >> 10;
    int n  = m & 1023;
    int gh = n >> 5, gw = n & 31;
    const float* abase = img + (size_t)bb * 33554432 + (size_t)(gh * 16) * 512 + gw * 16;
    const float* Bp = g_pw2 + (size_t)brow * 512 + n0 + bcol;

    float acc[4][4] = {};
    for (int k0 = 0; k0 < 32768; k0 += 16) {
        int k  = k0 + acol;
        int c  = k >> 8;
        int p1 = (k >> 4) & 15;
        int p2 = k & 15;
        float4 a  = *(const float4*)(abase + (size_t)c * 262144 + p1 * 512 + p2);
        float4 b4 = *(const float4*)Bp;
        Bp += (size_t)16 * 512;
        As[acol + 0][arow] = a.x; As[acol + 1][arow] = a.y;
        As[acol + 2][arow] = a.z; As[acol + 3][arow] = a.w;
        *(float4*)&Bs[brow][bcol] = b4;
        __syncthreads();
#pragma unroll
        for (int kk = 0; kk < 16; kk++) {
            float4 a4 = *(const float4*)&As[kk][ty << 2];
            float4 v4 = *(const float4*)&Bs[kk][tx << 2];
            float ar[4] = {a4.x, a4.y, a4.z, a4.w};
            float br[4] = {v4.x, v4.y, v4.z, v4.w};
#pragma unroll
            for (int i = 0; i < 4; i++)
#pragma unroll
                for (int j = 0; j < 4; j++) acc[i][j] += ar[i] * br[j];
        }
        __syncthreads();
    }
#pragma unroll
    for (int i = 0; i < 4; i++) {
        int mm  = m0 + (ty << 2) + i;
        int nn  = mm & 1023;
        int col = n0 + (tx << 2);
        float4 o;
        o.x = acc[i][0] + pb[col + 0] + pos[(size_t)nn * 512 + col + 0];
        o.y = acc[i][1] + pb[col + 1] + pos[(size_t)nn * 512 + col + 1];
        o.z = acc[i][2] + pb[col + 2] + pos[(size_t)nn * 512 + col + 2];
        o.w = acc[i][3] + pb[col + 3] + pos[(size_t)nn * 512 + col + 3];
        *(float4*)(g_x + (size_t)mm * 512 + col) = o;
    }
}

// ============================================================================
// generic SGEMM  C[M][Nd] = A[M][K] @ B[K][Nd]  (+bias)(+gelu)(+resid g_x)
// ============================================================================
__global__ __launch_bounds__(256)
void k_sgemm(int aId, const float* __restrict__ Bm, int cId, int Nd, int K,
             const float* __restrict__ bias, int addResid, int gelu) {
    __shared__ __align__(16) float As[16][64];
    __shared__ __align__(16) float Bs[16][64];
    const float* A = buf(aId);
    float* C = buf(cId);
    int tid = threadIdx.x;
    int m0 = blockIdx.y * 64;
    int n0 = blockIdx.x * 64;
    int arow = tid >> 2;
    int acol = (tid & 3) << 2;
    int brow = tid >> 4;
    int bcol = (tid & 15) << 2;
    int ty = tid >> 4, tx = tid & 15;

    const float* Ap = A + (size_t)(m0 + arow) * K + acol;
    const float* Bp = Bm + (size_t)brow * Nd + n0 + bcol;

    float acc[4][4] = {};
    for (int k0 = 0; k0 < K; k0 += 16) {
        float4 a  = *(const float4*)Ap;  Ap += 16;
        float4 b4 = *(const float4*)Bp;  Bp += (size_t)16 * Nd;
        As[acol + 0][arow] = a.x; As[acol + 1][arow] = a.y;
        As[acol + 2][arow] = a.z; As[acol + 3][arow] = a.w;
        *(float4*)&Bs[brow][bcol] = b4;
        __syncthreads();
#pragma unroll
        for (int kk = 0; kk < 16; kk++) {
            float4 a4 = *(const float4*)&As[kk][ty << 2];
            float4 v4 = *(const float4*)&Bs[kk][tx << 2];
            float ar[4] = {a4.x, a4.y, a4.z, a4.w};
            float br[4] = {v4.x, v4.y, v4.z, v4.w};
#pragma unroll
            for (int i = 0; i < 4; i++)
#pragma unroll
                for (int j = 0; j < 4; j++) acc[i][j] += ar[i] * br[j];
        }
        __syncthreads();
    }
#pragma unroll
    for (int i = 0; i < 4; i++) {
        int mm  = m0 + (ty << 2) + i;
        int col = n0 + (tx << 2);
        float r[4];
#pragma unroll
        for (int j = 0; j < 4; j++) {
            float val = acc[i][j];
            if (bias)     val += bias[col + j];
            if (gelu)     val = 0.5f * val * (1.0f + erff(val * 0.70710678118654752f));
            if (addResid) val += g_x[(size_t)mm * 512 + col + j];
            r[j] = val;
        }
        float4 o; o.x = r[0]; o.y = r[1]; o.z = r[2]; o.w = r[3];
        *(float4*)(C + (size_t)mm * Nd + col) = o;
    }
}

// ============================================================================
// attention scores:  S[z][i][j] = (Q_i . K_j)/8 + tbl[relidx(i,j)][head]
// ============================================================================
__global__ __launch_bounds__(256)
void k_attn_scores(const float* __restrict__ tbl, int qkvld, int inner, int hc) {
    __shared__ __align__(16) float Qs[16][64];
    __shared__ __align__(16) float Ks[16][64];
    int z = blockIdx.z;
    int bb = z / hc, head = z % hc;
    const float* Qb = g_qkv + (size_t)bb * 1024 * qkvld + head * 64;
    const float* Kb = Qb + inner;
    int tid = threadIdx.x;
    int arow = tid >> 2, acol = (tid & 3) << 2;
    int ty = tid >> 4, tx = tid & 15;
    int i0 = blockIdx.y * 64, j0 = blockIdx.x * 64;

    float acc[4][4] = {};
    for (int k0 = 0; k0 < 64; k0 += 16) {
        float4 q   = *(const float4*)(Qb + (size_t)(i0 + arow) * qkvld + k0 + acol);
        float4 kk4 = *(const float4*)(Kb + (size_t)(j0 + arow) * qkvld + k0 + acol);
        Qs[acol + 0][arow] = q.x; Qs[acol + 1][arow] = q.y;
        Qs[acol + 2][arow] = q.z; Qs[acol + 3][arow] = q.w;
        Ks[acol + 0][arow] = kk4.x; Ks[acol + 1][arow] = kk4.y;
        Ks[acol + 2][arow] = kk4.z; Ks[acol + 3][arow] = kk4.w;
        __syncthreads();
#pragma unroll
        for (int kk = 0; kk < 16; kk++) {
            float4 a4 = *(const float4*)&Qs[kk][ty << 2];
            float4 v4 = *(const float4*)&Ks[kk][tx << 2];
            float ar[4] = {a4.x, a4.y, a4.z, a4.w};
            float br[4] = {v4.x, v4.y, v4.z, v4.w};
#pragma unroll
            for (int i = 0; i < 4; i++)
#pragma unroll
                for (int j = 0; j < 4; j++) acc[i][j] += ar[i] * br[j];
        }
        __syncthreads();
    }
    float* Sp = g_attn + (size_t)z * 1048576;
#pragma unroll
    for (int i = 0; i < 4; i++) {
        int ii = i0 + (ty << 2) + i;
        int ih = ii >> 5, iw = ii & 31;
        float r[4];
#pragma unroll
        for (int j = 0; j < 4; j++) {
            int jj = j0 + (tx << 2) + j;
            int jh = jj >> 5, jw = jj & 31;
            int rel = (ih - jh + 31) * 63 + (iw - jw + 31);
            r[j] = acc[i][j] * 0.125f + tbl[(size_t)rel * hc + head];
        }
        float4 o; o.x = r[0]; o.y = r[1]; o.z = r[2]; o.w = r[3];
        *(float4*)(Sp + (size_t)ii * 1024 + j0 + (tx << 2)) = o;
    }
}

// ============================================================================
// row softmax over 1024 columns (one block = one row)
// ============================================================================
__global__ void k_softmax() {
    __shared__ float sh[8];
    int tid = threadIdx.x;
    float* row = g_attn + (size_t)blockIdx.x * 1024;
    float4 v = ((float4*)row)[tid];
    float m = fmaxf(fmaxf(v.x, v.y), fmaxf(v.z, v.w));
#pragma unroll
    for (int o = 16; o; o >>= 1) m = fmaxf(m, __shfl_xor_sync(0xffffffffu, m, o));
    if ((tid & 31) == 0) sh[tid >> 5] = m;
    __syncthreads();
    float m8 = sh[0];
#pragma unroll
    for (int i = 1; i < 8; i++) m8 = fmaxf(m8, sh[i]);
    float4 e;
    e.x = __expf(v.x - m8); e.y = __expf(v.y - m8);
    e.z = __expf(v.z - m8); e.w = __expf(v.w - m8);
    float s = e.x + e.y + e.z + e.w;
#pragma unroll
    for (int o = 16; o; o >>= 1) s += __shfl_xor_sync(0xffffffffu, s, o);
    __syncthreads();
    if ((tid & 31) == 0) sh[tid >> 5] = s;
    __syncthreads();
    float tot = 0.f;
#pragma unroll
    for (int i = 0; i < 8; i++) tot += sh[i];
    float inv = 1.0f / tot;
    e.x *= inv; e.y *= inv; e.z *= inv; e.w *= inv;
    ((float4*)row)[tid] = e;
}

// ============================================================================
// attn @ V:  g_o[b][i][head*64+d] = sum_j S[z][i][j] * V[b][j][head*64+d]
// ============================================================================
__global__ __launch_bounds__(256)
void k_attn_av(int qkvld, int inner, int hc) {
    __shared__ __align__(16) float As[16][64];
    __shared__ __align__(16) float Bs[16][64];
    int z = blockIdx.z;
    int bb = z / hc, head = z % hc;
    const float* Sp = g_attn + (size_t)z * 1048576;
    const float* Vb = g_qkv + (size_t)bb * 1024 * qkvld + 2 * inner + head * 64;
    int tid = threadIdx.x;
    int arow = tid >> 2, acol = (tid & 3) << 2;
    int brow = tid >> 4, bcol = (tid & 15) << 2;
    int ty = tid >> 4, tx = tid & 15;
    int i0 = blockIdx.y * 64;

    float acc[4][4] = {};
    for (int k0 = 0; k0 < 1024; k0 += 16) {
        float4 a  = *(const float4*)(Sp + (size_t)(i0 + arow) * 1024 + k0 + acol);
        float4 b4 = *(const float4*)(Vb + (size_t)(k0 + brow) * qkvld + bcol);
        As[acol + 0][arow] = a.x; As[acol + 1][arow] = a.y;
        As[acol + 2][arow] = a.z; As[acol + 3][arow] = a.w;
        *(float4*)&Bs[brow][bcol] = b4;
        __syncthreads();
#pragma unroll
        for (int kk = 0; kk < 16; kk++) {
            float4 a4 = *(const float4*)&As[kk][ty << 2];
            float4 v4 = *(const float4*)&Bs[kk][tx << 2];
            float ar[4] = {a4.x, a4.y, a4.z, a4.w};
            float br[4] = {v4.x, v4.y, v4.z, v4.w};
#pragma unroll
            for (int i = 0; i < 4; i++)
#pragma unroll
                for (int j = 0; j < 4; j++) acc[i][j] += ar[i] * br[j];
        }
        __syncthreads();
    }
#pragma unroll
    for (int i = 0; i < 4; i++) {
        int ii = i0 + (ty << 2) + i;
        float4 o;
        o.x = acc[i][0]; o.y = acc[i][1]; o.z = acc[i][2]; o.w = acc[i][3];
        *(float4*)(g_o + ((size_t)bb * 1024 + ii) * inner + head * 64 + (tx << 2)) = o;
    }
}

// ============================================================================
// LayerNorm over 512 (one block per row): reads g_x, writes g_xn
// ============================================================================
__global__ void k_layernorm(const float* __restrict__ s, const float* __restrict__ b) {
    __shared__ float ssum[4], ssq[4];
    int tid = threadIdx.x;
    int row = blockIdx.x;
    float4 v = ((const float4*)(g_x + (size_t)row * 512))[tid];
    float sum = v.x + v.y + v.z + v.w;
    float sq  = v.x * v.x + v.y * v.y + v.z * v.z + v.w * v.w;
#pragma unroll
    for (int o = 16; o; o >>= 1) {
        sum += __shfl_xor_sync(0xffffffffu, sum, o);
        sq  += __shfl_xor_sync(0xffffffffu, sq, o);
    }
    if ((tid & 31) == 0) { ssum[tid >> 5] = sum; ssq[tid >> 5] = sq; }
    __syncthreads();
    float ts = ssum[0] + ssum[1] + ssum[2] + ssum[3];
    float tq = ssq[0] + ssq[1] + ssq[2] + ssq[3];
    float mean = ts * (1.0f / 512.0f);
    float var  = tq * (1.0f / 512.0f) - mean * mean;
    float rstd = rsqrtf(var + 1e-5f);
    int d = tid << 2;
    float4 sv = *(const float4*)(s + d);
    float4 bv = *(const float4*)(b + d);
    float4 o;
    o.x = (v.x - mean) * rstd * sv.x + bv.x;
    o.y = (v.y - mean) * rstd * sv.y + bv.y;
    o.z = (v.z - mean) * rstd * sv.z + bv.z;
    o.w = (v.w - mean) * rstd * sv.w + bv.w;
    ((float4*)(g_xn + (size_t)row * 512))[tid] = o;
}

// ============================================================================
// final layout: out[b][d][n] = g_x[b][n][d]
// ============================================================================
__global__ void k_out(float* __restrict__ out) {
    __shared__ float t[32][33];
    int bb = blockIdx.z;
    int n0 = blockIdx.x * 32, d0 = blockIdx.y * 32;
    int tx = threadIdx.x, ty = threadIdx.y;   // 32 x 8
#pragma unroll
    for (int i = 0; i < 32; i += 8)
        t[ty + i][tx] = g_x[((size_t)bb * 1024 + n0 + ty + i) * 512 + d0 + tx];
    __syncthreads();
#pragma unroll
    for (int i = 0; i < 32; i += 8)
        out[((size_t)bb * 512 + d0 + ty + i) * 1024 + n0 + tx] = t[tx][ty + i];
}

// ============================================================================
// host orchestration
// ============================================================================
extern "C" void kernel_launch(void* const* d_in, const int* in_sizes, int n_in,
                              void* d_out, int out_size) {
    const float *img = 0, *patch_w = 0, *patch_b = 0, *pos_emb = 0;
    const float *ln1_s = 0, *ln1_b = 0, *ln2_s = 0, *ln2_b = 0;
    const float *qkv_w[3] = {0, 0, 0}, *out_w[3] = {0, 0, 0}, *out_b[3] = {0, 0, 0};
    const float *tbl[3] = {0, 0, 0};
    const float *ff_w1 = 0, *ff_b1 = 0, *ff_w2 = 0, *ff_b2 = 0;
    int c512 = 0, c1536 = 0, c393 = 0;
    for (int i = 0; i < n_in; i++) {
        const float* p = (const float*)d_in[i];
        switch (in_sizes[i]) {
            case 134217728: img = p; break;   // B*C*H*W = 4*128*512*512
            case 16777216: patch_w = p; break;
            case 524288:   pos_emb = p; break;
            case 512: {    // patch_b, out_b0, out_b1, out_b2 (same relative order
                           // under dict- or signature-ordering of the metadata)
                const float** t[4] = {&patch_b, &out_b[0], &out_b[1], &out_b[2]};
                if (c512 < 4) *t[c512] = p;
                c512++;
            } break;
            case 1536: {   // ln1_s, ln1_b, ln2_s, ln2_b, ff_b2
                const float** t[5] = {&ln1_s, &ln1_b, &ln2_s, &ln2_b, &ff_b2};
                if (c1536 < 5) *t[c1536] = p;
                c1536++;
            } break;
            case 768:    ff_b1 = p; break;
            case 196608: qkv_w[0] = p; break;
            case 393216: {  // qkv_w1, ff_w1, ff_w2
                const float** t[3] = {&qkv_w[1], &ff_w1, &ff_w2};
                if (c393 < 3) *t[c393] = p;
                c393++;
            } break;
            case 786432: qkv_w[2] = p; break;
            case 65536:  out_w[0] = p; break;
            case 131072: out_w[1] = p; break;
            case 262144: out_w[2] = p; break;
            case 7938:   tbl[0] = p; break;
            case 15876:  tbl[1] = p; break;
            case 31752:  tbl[2] = p; break;
            default: break;
        }
    }

    // defensive: never launch with a null base pointer
    bool ok = img && patch_w && patch_b && pos_emb && ln1_s && ln1_b && ln2_s &&
              ln2_b && ff_w1 && ff_b1 && ff_w2 && ff_b2;
    for (int l = 0; l < 3; l++)
        ok = ok && qkv_w[l] && out_w[l] && out_b[l] && tbl[l];
    if (!ok) {
        k_zero<<<(out_size + 255) / 256, 256>>>((float*)d_out, out_size);
        return;
    }

    // 1. permute patch_w, 2. patch-embed GEMM (fused bias + pos_emb)
    k_permute_pw<<<(32768 * 128 + 255) / 256, 256>>>(patch_w);
    k_patch_gemm<<<dim3(8, 64), 256>>>(img, patch_b, pos_emb);

    const int heads[3] = {2, 4, 8};
    for (int l = 0; l < 3; l++) {
        int h = heads[l];
        int inner = 64 * h;
        int qkvld = 3 * inner;
        // attention
        k_layernorm<<<4096, 128>>>(ln1_s + l * 512, ln1_b + l * 512);
        k_sgemm<<<dim3(qkvld / 64, 64), 256>>>(BUF_XN, qkv_w[l], BUF_QKV,
                                               qkvld, 512, nullptr, 0, 0);
        k_attn_scores<<<dim3(16, 16, 4 * h), 256>>>(tbl[l], qkvld, inner, h);
        k_softmax<<<4 * h * 1024, 256>>>();
        k_attn_av<<<dim3(1, 16, 4 * h), 256>>>(qkvld, inner, h);
        k_sgemm<<<dim3(8, 64), 256>>>(BUF_O, out_w[l], BUF_X,
                                      512, inner, out_b[l], 1, 0);
        // feed-forward
        k_layernorm<<<4096, 128>>>(ln2_s + l * 512, ln2_b + l * 512);
        k_sgemm<<<dim3(4, 64), 256>>>(BUF_XN, ff_w1 + (size_t)l * 512 * 256, BUF_H,
                                      256, 512, ff_b1 + l * 256, 0, 1);
        k_sgemm<<<dim3(8, 64), 256>>>(BUF_H, ff_w2 + (size_t)l * 256 * 512, BUF_X,
                                      512, 256, ff_b2 + l * 512, 1, 0);
    }

    // final [B, DIM, GH, GW] layout
    k_out<<<dim3(32, 16, 4), dim3(32, 8)>>>((float*)d_out);
}

// round 4
// speedup vs baseline: 2.1865x; 2.1865x over previous
#include <cuda_runtime.h>
#include <math.h>
#include <stdint.h>

// ---------------- problem constants ----------------
// B=4, C=128, H=W=512, P=16, GH=GW=32, N=1024, PATCH_DIM=32768, DIM=512,
// MLP=256, DH=64, HEADS=(2,4,8), NUM_REL=3969

// ---------------- scratch (device globals) ----------------
__device__ __align__(16) float g_pw2[32768 * 512];   // permuted patch_w (64 MB)
__device__ __align__(16) float g_x[4096 * 512];      // residual stream
__device__ __align__(16) float g_xn[4096 * 512];     // LN output
__device__ __align__(16) float g_qkv[4096 * 1536];   // qkv (max inner=512)
__device__ __align__(16) float g_attn[33554432];     // scores, B*8*N*N (128 MB)
__device__ __align__(16) float g_o[4096 * 512];      // attention output
__device__ __align__(16) float g_h[4096 * 256];      // FFN hidden

#define BUF_X   0
#define BUF_XN  1
#define BUF_QKV 2
#define BUF_O   3
#define BUF_H   4
__device__ __forceinline__ float* buf(int id) {
    switch (id) {
        case BUF_X:   return g_x;
        case BUF_XN:  return g_xn;
        case BUF_QKV: return g_qkv;
        case BUF_O:   return g_o;
        default:      return g_h;
    }
}

// ============================================================================
__global__ void k_zero(float* o, int n) {
    int i = blockIdx.x * blockDim.x + threadIdx.x;
    if (i < n) o[i] = 0.0f;
}

// ============================================================================
// permute patch_w rows:  in row (p1*16+p2)*128 + c  ->  out row c*256 + p1*16+p2
// ============================================================================
__global__ void k_permute_pw(const float* __restrict__ pw) {
    int idx = blockIdx.x * blockDim.x + threadIdx.x;   // 32768 rows * 128 float4
    if (idx >= 32768 * 128) return;
    int r  = idx >> 7;
    int d4 = idx & 127;
    int p  = r >> 7;       // p1*16+p2
    int c  = r & 127;
    int rout = (c << 8) + p;
    float4 v = ((const float4*)pw)[(size_t)r * 128 + d4];
    ((float4*)g_pw2)[(size_t)rout * 128 + d4] = v;
}

// ============================================================================
// TF32 tensor-core helpers
// ============================================================================
__device__ __forceinline__ uint32_t f2tf(float f) {
    uint32_t r;
    asm("cvt.rna.tf32.f32 %0, %1;" : "=r"(r) : "f"(f));
    return r;
}
__device__ __forceinline__ void mma_tf32(float c[4], const uint32_t a[4],
                                         const uint32_t b[2]) {
    asm("mma.sync.aligned.m16n8k8.row.col.f32.tf32.tf32.f32 "
        "{%0,%1,%2,%3},{%4,%5,%6,%7},{%8,%9},{%0,%1,%2,%3};"
        : "+f"(c[0]), "+f"(c[1]), "+f"(c[2]), "+f"(c[3])
        : "r"(a[0]), "r"(a[1]), "r"(a[2]), "r"(a[3]), "r"(b[0]), "r"(b[1]));
}

// ============================================================================
// patch embed GEMM on tensor cores (TF32):
//   g_x[m][d] = sum_k' A[m][k'] * pw2[k'][d] + pb[d] + pos[n][d]
//   A gathered from img: k' = c*256 + p1*16 + p2
// CTA tile 128x128, BK=32, 8 warps (warp tile 32m x 64n), double-buffered.
// ============================================================================
__global__ __launch_bounds__(256, 1)
void k_patch_tc(const float* __restrict__ img,
                const float* __restrict__ pb,
                const float* __restrict__ pos) {
    // As: per m-row 32 floats, float4-chunk xor-swizzled by (m&7)
    // Bs: [k][n] with row pad to 136 floats
    __shared__ __align__(16) float As[2][128 * 32];
    __shared__ __align__(16) float Bs[2][32 * 136];

    const int tid  = threadIdx.x;
    const int lane = tid & 31;
    const int wid  = tid >> 5;
    const int warp_m = (wid & 3) * 32;   // 4 warps along m
    const int warp_n = (wid >> 2) * 64;  // 2 warps along n
    const int m0 = blockIdx.y * 128;
    const int n0 = blockIdx.x * 128;

    // A gather mapping: tid%8 = k-quad, tid/8 = m row (stride 32, x4)
    const int aq = tid & 7;
    const int am = tid >> 3;
    // B load mapping: tid%32 = n float4-chunk, tid/32 = k row (stride 8, x4)
    const int bc = tid & 31;
    const int bk = tid >> 5;

    const float* abase[4];
#pragma unroll
    for (int t = 0; t < 4; t++) {
        int m_g = m0 + am + t * 32;
        int bb  = m_g >> 10;
        int tok = m_g & 1023;
        int gh = tok >> 5, gw = tok & 31;
        abase[t] = img + (size_t)bb * 33554432 + (size_t)(gh * 16) * 512 + gw * 16;
    }
    const float* bbase = g_pw2 + n0 + bc * 4;

    // smem store offsets (constant per thread)
    const int awoff = am * 32 + ((aq ^ (am & 7)) << 2);   // + t*1024
    const int bwoff = bk * 136 + bc * 4;                  // + t*8*136

    float c[2][8][4];
#pragma unroll
    for (int i = 0; i < 2; i++)
#pragma unroll
        for (int j = 0; j < 8; j++)
#pragma unroll
            for (int q = 0; q < 4; q++) c[i][j][q] = 0.0f;

    float4 pa[4], pv[4];

    // ---- prologue: load k0 = 0 ----
    {
        int k = aq * 4;
        int cc = k >> 8, rem = k & 255;
        const size_t aoff = (size_t)cc * 262144 + (rem >> 4) * 512 + (rem & 15);
#pragma unroll
        for (int t = 0; t < 4; t++) pa[t] = *(const float4*)(abase[t] + aoff);
#pragma unroll
        for (int t = 0; t < 4; t++)
            pv[t] = *(const float4*)(bbase + (size_t)(bk + t * 8) * 512);
#pragma unroll
        for (int t = 0; t < 4; t++) *(float4*)&As[0][awoff + t * 1024] = pa[t];
#pragma unroll
        for (int t = 0; t < 4; t++) *(float4*)&Bs[0][bwoff + t * 8 * 136] = pv[t];
    }
    __syncthreads();

    int bsel = 0;
    for (int it = 0; it < 1024; it++) {
        if (it < 1023) {
            int k0 = (it + 1) * 32;
            int k = k0 + aq * 4;
            int cc = k >> 8, rem = k & 255;
            const size_t aoff = (size_t)cc * 262144 + (rem >> 4) * 512 + (rem & 15);
#pragma unroll
            for (int t = 0; t < 4; t++) pa[t] = *(const float4*)(abase[t] + aoff);
#pragma unroll
            for (int t = 0; t < 4; t++)
                pv[t] = *(const float4*)(bbase + (size_t)(k0 + bk + t * 8) * 512);
        }

        const float* Asb = As[bsel];
        const float* Bsb = Bs[bsel];
#pragma unroll
        for (int kk = 0; kk < 4; kk++) {
            uint32_t af[2][4], bf[8][2];
            const int kq0 = kk * 2, kq1 = kk * 2 + 1;
            const int kb  = lane & 3;
#pragma unroll
            for (int ma = 0; ma < 2; ma++) {
                int r0 = warp_m + ma * 16 + (lane >> 2);
                int r1 = r0 + 8;
                af[ma][0] = f2tf(Asb[r0 * 32 + ((kq0 ^ (r0 & 7)) << 2) + kb]);
                af[ma][1] = f2tf(Asb[r1 * 32 + ((kq0 ^ (r1 & 7)) << 2) + kb]);
                af[ma][2] = f2tf(Asb[r0 * 32 + ((kq1 ^ (r0 & 7)) << 2) + kb]);
                af[ma][3] = f2tf(Asb[r1 * 32 + ((kq1 ^ (r1 & 7)) << 2) + kb]);
            }
#pragma unroll
            for (int na = 0; na < 8; na++) {
                int n = warp_n + na * 8 + (lane >> 2);
                bf[na][0] = f2tf(Bsb[(kk * 8 + kb) * 136 + n]);
                bf[na][1] = f2tf(Bsb[(kk * 8 + 4 + kb) * 136 + n]);
            }
#pragma unroll
            for (int ma = 0; ma < 2; ma++)
#pragma unroll
                for (int na = 0; na < 8; na++)
                    mma_tf32(c[ma][na], af[ma], bf[na]);
        }

        if (it < 1023) {
            int nb = bsel ^ 1;
#pragma unroll
            for (int t = 0; t < 4; t++) *(float4*)&As[nb][awoff + t * 1024] = pa[t];
#pragma unroll
            for (int t = 0; t < 4; t++) *(float4*)&Bs[nb][bwoff + t * 8 * 136] = pv[t];
            __syncthreads();
            bsel = nb;
        }
    }

    // ---- epilogue: + patch_b + pos_emb, write g_x ----
#pragma unroll
    for (int ma = 0; ma < 2; ma++) {
        int r0 = m0 + warp_m + ma * 16 + (lane >> 2);
        int r1 = r0 + 8;
        int tok0 = r0 & 1023, tok1 = r1 & 1023;
#pragma unroll
        for (int na = 0; na < 8; na++) {
            int col = n0 + warp_n + na * 8 + (lane & 3) * 2;
            float2 o0, o1;
            o0.x = c[ma][na][0] + pb[col]     + pos[(size_t)tok0 * 512 + col];
            o0.y = c[ma][na][1] + pb[col + 1] + pos[(size_t)tok0 * 512 + col + 1];
            o1.x = c[ma][na][2] + pb[col]     + pos[(size_t)tok1 * 512 + col];
            o1.y = c[ma][na][3] + pb[col + 1] + pos[(size_t)tok1 * 512 + col + 1];
            *(float2*)(g_x + (size_t)r0 * 512 + col) = o0;
            *(float2*)(g_x + (size_t)r1 * 512 + col) = o1;
        }
    }
}

// ============================================================================
// generic SGEMM  C[M][Nd] = A[M][K] @ B[K][Nd]  (+bias)(+gelu)(+resid g_x)
// ============================================================================
__global__ __launch_bounds__(256)
void k_sgemm(int aId, const float* __restrict__ Bm, int cId, int Nd, int K,
             const float* __restrict__ bias, int addResid, int gelu) {
    __shared__ __align__(16) float As[16][64];
    __shared__ __align__(16) float Bs[16][64];
    const float* A = buf(aId);
    float* C = buf(cId);
    int tid = threadIdx.x;
    int m0 = blockIdx.y * 64;
    int n0 = blockIdx.x * 64;
    int arow = tid >> 2;
    int acol = (tid & 3) << 2;
    int brow = tid >> 4;
    int bcol = (tid & 15) << 2;
    int ty = tid >> 4, tx = tid & 15;

    const float* Ap = A + (size_t)(m0 + arow) * K + acol;
    const float* Bp = Bm + (size_t)brow * Nd + n0 + bcol;

    float acc[4][4] = {};
    for (int k0 = 0; k0 < K; k0 += 16) {
        float4 a  = *(const float4*)Ap;  Ap += 16;
        float4 b4 = *(const float4*)Bp;  Bp += (size_t)16 * Nd;
        As[acol + 0][arow] = a.x; As[acol + 1][arow] = a.y;
        As[acol + 2][arow] = a.z; As[acol + 3][arow] = a.w;
        *(float4*)&Bs[brow][bcol] = b4;
        __syncthreads();
#pragma unroll
        for (int kk = 0; kk < 16; kk++) {
            float4 a4 = *(const float4*)&As[kk][ty << 2];
            float4 v4 = *(const float4*)&Bs[kk][tx << 2];
            float ar[4] = {a4.x, a4.y, a4.z, a4.w};
            float br[4] = {v4.x, v4.y, v4.z, v4.w};
#pragma unroll
            for (int i = 0; i < 4; i++)
#pragma unroll
                for (int j = 0; j < 4; j++) acc[i][j] += ar[i] * br[j];
        }
        __syncthreads();
    }
#pragma unroll
    for (int i = 0; i < 4; i++) {
        int mm  = m0 + (ty << 2) + i;
        int col = n0 + (tx << 2);
        float r[4];
#pragma unroll
        for (int j = 0; j < 4; j++) {
            float val = acc[i][j];
            if (bias)     val += bias[col + j];
            if (gelu)     val = 0.5f * val * (1.0f + erff(val * 0.70710678118654752f));
            if (addResid) val += g_x[(size_t)mm * 512 + col + j];
            r[j] = val;
        }
        float4 o; o.x = r[0]; o.y = r[1]; o.z = r[2]; o.w = r[3];
        *(float4*)(C + (size_t)mm * Nd + col) = o;
    }
}

// ============================================================================
// attention scores:  S[z][i][j] = (Q_i . K_j)/8 + tbl[relidx(i,j)][head]
// ============================================================================
__global__ __launch_bounds__(256)
void k_attn_scores(const float* __restrict__ tbl, int qkvld, int inner, int hc) {
    __shared__ __align__(16) float Qs[16][64];
    __shared__ __align__(16) float Ks[16][64];
    int z = blockIdx.z;
    int bb = z / hc, head = z % hc;
    const float* Qb = g_qkv + (size_t)bb * 1024 * qkvld + head * 64;
    const float* Kb = Qb + inner;
    int tid = threadIdx.x;
    int arow = tid >> 2, acol = (tid & 3) << 2;
    int ty = tid >> 4, tx = tid & 15;
    int i0 = blockIdx.y * 64, j0 = blockIdx.x * 64;

    float acc[4][4] = {};
    for (int k0 = 0; k0 < 64; k0 += 16) {
        float4 q   = *(const float4*)(Qb + (size_t)(i0 + arow) * qkvld + k0 + acol);
        float4 kk4 = *(const float4*)(Kb + (size_t)(j0 + arow) * qkvld + k0 + acol);
        Qs[acol + 0][arow] = q.x; Qs[acol + 1][arow] = q.y;
        Qs[acol + 2][arow] = q.z; Qs[acol + 3][arow] = q.w;
        Ks[acol + 0][arow] = kk4.x; Ks[acol + 1][arow] = kk4.y;
        Ks[acol + 2][arow] = kk4.z; Ks[acol + 3][arow] = kk4.w;
        __syncthreads();
#pragma unroll
        for (int kk = 0; kk < 16; kk++) {
            float4 a4 = *(const float4*)&Qs[kk][ty << 2];
            float4 v4 = *(const float4*)&Ks[kk][tx << 2];
            float ar[4] = {a4.x, a4.y, a4.z, a4.w};
            float br[4] = {v4.x, v4.y, v4.z, v4.w};
#pragma unroll
            for (int i = 0; i < 4; i++)
#pragma unroll
                for (int j = 0; j < 4; j++) acc[i][j] += ar[i] * br[j];
        }
        __syncthreads();
    }
    float* Sp = g_attn + (size_t)z * 1048576;
#pragma unroll
    for (int i = 0; i < 4; i++) {
        int ii = i0 + (ty << 2) + i;
        int ih = ii >> 5, iw = ii & 31;
        float r[4];
#pragma unroll
        for (int j = 0; j < 4; j++) {
            int jj = j0 + (tx << 2) + j;
            int jh = jj >> 5, jw = jj & 31;
            int rel = (ih - jh + 31) * 63 + (iw - jw + 31);
            r[j] = acc[i][j] * 0.125f + tbl[(size_t)rel * hc + head];
        }
        float4 o; o.x = r[0]; o.y = r[1]; o.z = r[2]; o.w = r[3];
        *(float4*)(Sp + (size_t)ii * 1024 + j0 + (tx << 2)) = o;
    }
}

// ============================================================================
// row softmax over 1024 columns (one block = one row)
// ============================================================================
__global__ void k_softmax() {
    __shared__ float sh[8];
    int tid = threadIdx.x;
    float* row = g_attn + (size_t)blockIdx.x * 1024;
    float4 v = ((float4*)row)[tid];
    float m = fmaxf(fmaxf(v.x, v.y), fmaxf(v.z, v.w));
#pragma unroll
    for (int o = 16; o; o >>= 1) m = fmaxf(m, __shfl_xor_sync(0xffffffffu, m, o));
    if ((tid & 31) == 0) sh[tid >> 5] = m;
    __syncthreads();
    float m8 = sh[0];
#pragma unroll
    for (int i = 1; i < 8; i++) m8 = fmaxf(m8, sh[i]);
    float4 e;
    e.x = __expf(v.x - m8); e.y = __expf(v.y - m8);
    e.z = __expf(v.z - m8); e.w = __expf(v.w - m8);
    float s = e.x + e.y + e.z + e.w;
#pragma unroll
    for (int o = 16; o; o >>= 1) s += __shfl_xor_sync(0xffffffffu, s, o);
    __syncthreads();
    if ((tid & 31) == 0) sh[tid >> 5] = s;
    __syncthreads();
    float tot = 0.f;
#pragma unroll
    for (int i = 0; i < 8; i++) tot += sh[i];
    float inv = 1.0f / tot;
    e.x *= inv; e.y *= inv; e.z *= inv; e.w *= inv;
    ((float4*)row)[tid] = e;
}

// ============================================================================
// attn @ V:  g_o[b][i][head*64+d] = sum_j S[z][i][j] * V[b][j][head*64+d]
// ============================================================================
__global__ __launch_bounds__(256)
void k_attn_av(int qkvld, int inner, int hc) {
    __shared__ __align__(16) float As[16][64];
    __shared__ __align__(16) float Bs[16][64];
    int z = blockIdx.z;
    int bb = z / hc, head = z % hc;
    const float* Sp = g_attn + (size_t)z * 1048576;
    const float* Vb = g_qkv + (size_t)bb * 1024 * qkvld + 2 * inner + head * 64;
    int tid = threadIdx.x;
    int arow = tid >> 2, acol = (tid & 3) << 2;
    int brow = tid >> 4, bcol = (tid & 15) << 2;
    int ty = tid >> 4, tx = tid & 15;
    int i0 = blockIdx.y * 64;

    float acc[4][4] = {};
    for (int k0 = 0; k0 < 1024; k0 += 16) {
        float4 a  = *(const float4*)(Sp + (size_t)(i0 + arow) * 1024 + k0 + acol);
        float4 b4 = *(const float4*)(Vb + (size_t)(k0 + brow) * qkvld + bcol);
        As[acol + 0][arow] = a.x; As[acol + 1][arow] = a.y;
        As[acol + 2][arow] = a.z; As[acol + 3][arow] = a.w;
        *(float4*)&Bs[brow][bcol] = b4;
        __syncthreads();
#pragma unroll
        for (int kk = 0; kk < 16; kk++) {
            float4 a4 = *(const float4*)&As[kk][ty << 2];
            float4 v4 = *(const float4*)&Bs[kk][tx << 2];
            float ar[4] = {a4.x, a4.y, a4.z, a4.w};
            float br[4] = {v4.x, v4.y, v4.z, v4.w};
#pragma unroll
            for (int i = 0; i < 4; i++)
#pragma unroll
                for (int j = 0; j < 4; j++) acc[i][j] += ar[i] * br[j];
        }
        __syncthreads();
    }
#pragma unroll
    for (int i = 0; i < 4; i++) {
        int ii = i0 + (ty << 2) + i;
        float4 o;
        o.x = acc[i][0]; o.y = acc[i][1]; o.z = acc[i][2]; o.w = acc[i][3];
        *(float4*)(g_o + ((size_t)bb * 1024 + ii) * inner + head * 64 + (tx << 2)) = o;
    }
}

// ============================================================================
// LayerNorm over 512 (one block per row): reads g_x, writes g_xn
// ============================================================================
__global__ void k_layernorm(const float* __restrict__ s, const float* __restrict__ b) {
    __shared__ float ssum[4], ssq[4];
    int tid = threadIdx.x;
    int row = blockIdx.x;
    float4 v = ((const float4*)(g_x + (size_t)row * 512))[tid];
    float sum = v.x + v.y + v.z + v.w;
    float sq  = v.x * v.x + v.y * v.y + v.z * v.z + v.w * v.w;
#pragma unroll
    for (int o = 16; o; o >>= 1) {
        sum += __shfl_xor_sync(0xffffffffu, sum, o);
        sq  += __shfl_xor_sync(0xffffffffu, sq, o);
    }
    if ((tid & 31) == 0) { ssum[tid >> 5] = sum; ssq[tid >> 5] = sq; }
    __syncthreads();
    float ts = ssum[0] + ssum[1] + ssum[2] + ssum[3];
    float tq = ssq[0] + ssq[1] + ssq[2] + ssq[3];
    float mean = ts * (1.0f / 512.0f);
    float var  = tq * (1.0f / 512.0f) - mean * mean;
    float rstd = rsqrtf(var + 1e-5f);
    int d = tid << 2;
    float4 sv = *(const float4*)(s + d);
    float4 bv = *(const float4*)(b + d);
    float4 o;
    o.x = (v.x - mean) * rstd * sv.x + bv.x;
    o.y = (v.y - mean) * rstd * sv.y + bv.y;
    o.z = (v.z - mean) * rstd * sv.z + bv.z;
    o.w = (v.w - mean) * rstd * sv.w + bv.w;
    ((float4*)(g_xn + (size_t)row * 512))[tid] = o;
}

// ============================================================================
// final layout: out[b][d][n] = g_x[b][n][d]
// ============================================================================
__global__ void k_out(float* __restrict__ out) {
    __shared__ float t[32][33];
    int bb = blockIdx.z;
    int n0 = blockIdx.x * 32, d0 = blockIdx.y * 32;
    int tx = threadIdx.x, ty = threadIdx.y;   // 32 x 8
#pragma unroll
    for (int i = 0; i < 32; i += 8)
        t[ty + i][tx] = g_x[((size_t)bb * 1024 + n0 + ty + i) * 512 + d0 + tx];
    __syncthreads();
#pragma unroll
    for (int i = 0; i < 32; i += 8)
        out[((size_t)bb * 512 + d0 + ty + i) * 1024 + n0 + tx] = t[tx][ty + i];
}

// ============================================================================
// host orchestration
// ============================================================================
extern "C" void kernel_launch(void* const* d_in, const int* in_sizes, int n_in,
                              void* d_out, int out_size) {
    const float *img = 0, *patch_w = 0, *patch_b = 0, *pos_emb = 0;
    const float *ln1_s = 0, *ln1_b = 0, *ln2_s = 0, *ln2_b = 0;
    const float *qkv_w[3] = {0, 0, 0}, *out_w[3] = {0, 0, 0}, *out_b[3] = {0, 0, 0};
    const float *tbl[3] = {0, 0, 0};
    const float *ff_w1 = 0, *ff_b1 = 0, *ff_w2 = 0, *ff_b2 = 0;
    int c512 = 0, c1536 = 0, c393 = 0;
    for (int i = 0; i < n_in; i++) {
        const float* p = (const float*)d_in[i];
        switch (in_sizes[i]) {
            case 134217728: img = p; break;   // B*C*H*W
            case 16777216: patch_w = p; break;
            case 524288:   pos_emb = p; break;
            case 512: {
                const float** t[4] = {&patch_b, &out_b[0], &out_b[1], &out_b[2]};
                if (c512 < 4) *t[c512] = p;
                c512++;
            } break;
            case 1536: {
                const float** t[5] = {&ln1_s, &ln1_b, &ln2_s, &ln2_b, &ff_b2};
                if (c1536 < 5) *t[c1536] = p;
                c1536++;
            } break;
            case 768:    ff_b1 = p; break;
            case 196608: qkv_w[0] = p; break;
            case 393216: {
                const float** t[3] = {&qkv_w[1], &ff_w1, &ff_w2};
                if (c393 < 3) *t[c393] = p;
                c393++;
            } break;
            case 786432: qkv_w[2] = p; break;
            case 65536:  out_w[0] = p; break;
            case 131072: out_w[1] = p; break;
            case 262144: out_w[2] = p; break;
            case 7938:   tbl[0] = p; break;
            case 15876:  tbl[1] = p; break;
            case 31752:  tbl[2] = p; break;
            default: break;
        }
    }

    bool ok = img && patch_w && patch_b && pos_emb && ln1_s && ln1_b && ln2_s &&
              ln2_b && ff_w1 && ff_b1 && ff_w2 && ff_b2;
    for (int l = 0; l < 3; l++)
        ok = ok && qkv_w[l] && out_w[l] && out_b[l] && tbl[l];
    if (!ok) {
        k_zero<<<(out_size + 255) / 256, 256>>>((float*)d_out, out_size);
        return;
    }

    // 1. permute patch_w, 2. patch-embed GEMM on tensor cores (TF32)
    k_permute_pw<<<(32768 * 128 + 255) / 256, 256>>>(patch_w);
    k_patch_tc<<<dim3(4, 32), 256>>>(img, patch_b, pos_emb);

    const int heads[3] = {2, 4, 8};
    for (int l = 0; l < 3; l++) {
        int h = heads[l];
        int inner = 64 * h;
        int qkvld = 3 * inner;
        // attention
        k_layernorm<<<4096, 128>>>(ln1_s + l * 512, ln1_b + l * 512);
        k_sgemm<<<dim3(qkvld / 64, 64), 256>>>(BUF_XN, qkv_w[l], BUF_QKV,
                                               qkvld, 512, nullptr, 0, 0);
        k_attn_scores<<<dim3(16, 16, 4 * h), 256>>>(tbl[l], qkvld, inner, h);
        k_softmax<<<4 * h * 1024, 256>>>();
        k_attn_av<<<dim3(1, 16, 4 * h), 256>>>(qkvld, inner, h);
        k_sgemm<<<dim3(8, 64), 256>>>(BUF_O, out_w[l], BUF_X,
                                      512, inner, out_b[l], 1, 0);
        // feed-forward
        k_layernorm<<<4096, 128>>>(ln2_s + l * 512, ln2_b + l * 512);
        k_sgemm<<<dim3(4, 64), 256>>>(BUF_XN, ff_w1 + (size_t)l * 512 * 256, BUF_H,
                                      256, 512, ff_b1 + l * 256, 0, 1);
        k_sgemm<<<dim3(8, 64), 256>>>(BUF_H, ff_w2 + (size_t)l * 256 * 512, BUF_X,
                                      512, 256, ff_b2 + l * 512, 1, 0);
    }

    // final [B, DIM, GH, GW] layout
    k_out<<<dim3(32, 16, 4), dim3(32, 8)>>>((float*)d_out);
}

// round 5
// speedup vs baseline: 3.0139x; 1.3784x over previous
#include <cuda_runtime.h>
#include <math.h>
#include <stdint.h>

// ---------------- problem constants ----------------
// B=4, C=128, H=W=512, P=16, GH=GW=32, N=1024, PATCH_DIM=32768, DIM=512,
// MLP=256, DH=64, HEADS=(2,4,8), NUM_REL=3969

// ---------------- scratch (device globals) ----------------
__device__ __align__(16) float g_pw2[32768 * 512];   // permuted patch_w (64 MB)
__device__ __align__(16) float g_x[4096 * 512];      // residual stream
__device__ __align__(16) float g_xn[4096 * 512];     // LN output
__device__ __align__(16) float g_qkv[4096 * 1536];   // qkv (max inner=512)
__device__ __align__(16) float g_attn[33554432];     // scores, B*8*N*N (128 MB)
__device__ __align__(16) float g_o[4096 * 512];      // attention output
__device__ __align__(16) float g_h[4096 * 256];      // FFN hidden

#define BUF_X   0
#define BUF_XN  1
#define BUF_QKV 2
#define BUF_O   3
#define BUF_H   4
#define BUF_ATT 5
__device__ __forceinline__ float* buf(int id) {
    switch (id) {
        case BUF_X:   return g_x;
        case BUF_XN:  return g_xn;
        case BUF_QKV: return g_qkv;
        case BUF_O:   return g_o;
        case BUF_ATT: return g_attn;
        default:      return g_h;
    }
}

// ============================================================================
__global__ void k_zero(float* o, int n) {
    int i = blockIdx.x * blockDim.x + threadIdx.x;
    if (i < n) o[i] = 0.0f;
}

// ============================================================================
// permute patch_w rows:  in row (p1*16+p2)*128 + c  ->  out row c*256 + p1*16+p2
// ============================================================================
__global__ void k_permute_pw(const float* __restrict__ pw) {
    int idx = blockIdx.x * blockDim.x + threadIdx.x;   // 32768 rows * 128 float4
    if (idx >= 32768 * 128) return;
    int r  = idx >> 7;
    int d4 = idx & 127;
    int p  = r >> 7;       // p1*16+p2
    int c  = r & 127;
    int rout = (c << 8) + p;
    float4 v = ((const float4*)pw)[(size_t)r * 128 + d4];
    ((float4*)g_pw2)[(size_t)rout * 128 + d4] = v;
}

// ============================================================================
// TF32 helpers
// ============================================================================
__device__ __forceinline__ uint32_t f2tf(float f) {
    uint32_t r;
    asm("cvt.rna.tf32.f32 %0, %1;" : "=r"(r) : "f"(f));
    return r;
}
__device__ __forceinline__ float4 cvt4(float4 v) {
    v.x = __uint_as_float(f2tf(v.x));
    v.y = __uint_as_float(f2tf(v.y));
    v.z = __uint_as_float(f2tf(v.z));
    v.w = __uint_as_float(f2tf(v.w));
    return v;
}
__device__ __forceinline__ void mma_tf32(float c[4], const uint32_t a[4],
                                         const uint32_t b[2]) {
    asm("mma.sync.aligned.m16n8k8.row.col.f32.tf32.tf32.f32 "
        "{%0,%1,%2,%3},{%4,%5,%6,%7},{%8,%9},{%0,%1,%2,%3};"
        : "+f"(c[0]), "+f"(c[1]), "+f"(c[2]), "+f"(c[3])
        : "r"(a[0]), "r"(a[1]), "r"(a[2]), "r"(a[3]), "r"(b[0]), "r"(b[1]));
}
__device__ __forceinline__ uint32_t ldu(const float* p) {
    return __float_as_uint(*p);
}

// ============================================================================
// patch embed GEMM on tensor cores (TF32, cvt-on-store):
//   g_x[m][d] = sum_k' A[m][k'] * pw2[k'][d] + pb[d] + pos[n][d]
// CTA tile 128x128, BK=32, 8 warps, double-buffered.
// ============================================================================
__global__ __launch_bounds__(256, 1)
void k_patch_tc(const float* __restrict__ img,
                const float* __restrict__ pb,
                const float* __restrict__ pos) {
    __shared__ __align__(16) float As[2][128 * 32];
    __shared__ __align__(16) float Bs[2][32 * 136];

    const int tid  = threadIdx.x;
    const int lane = tid & 31;
    const int wid  = tid >> 5;
    const int warp_m = (wid & 3) * 32;
    const int warp_n = (wid >> 2) * 64;
    const int m0 = blockIdx.y * 128;
    const int n0 = blockIdx.x * 128;

    const int aq = tid & 7;
    const int am = tid >> 3;
    const int bc = tid & 31;
    const int bk = tid >> 5;

    const float* abase[4];
#pragma unroll
    for (int t = 0; t < 4; t++) {
        int m_g = m0 + am + t * 32;
        int bb  = m_g >> 10;
        int tok = m_g & 1023;
        int gh = tok >> 5, gw = tok & 31;
        abase[t] = img + (size_t)bb * 33554432 + (size_t)(gh * 16) * 512 + gw * 16;
    }
    const float* bbase = g_pw2 + n0 + bc * 4;

    const int awoff = am * 32 + ((aq ^ (am & 7)) << 2);
    const int bwoff = bk * 136 + bc * 4;

    float c[2][8][4];
#pragma unroll
    for (int i = 0; i < 2; i++)
#pragma unroll
        for (int j = 0; j < 8; j++)
#pragma unroll
            for (int q = 0; q < 4; q++) c[i][j][q] = 0.0f;

    float4 pa[4], pv[4];

    {
        int k = aq * 4;
        int cc = k >> 8, rem = k & 255;
        const size_t aoff = (size_t)cc * 262144 + (rem >> 4) * 512 + (rem & 15);
#pragma unroll
        for (int t = 0; t < 4; t++) pa[t] = *(const float4*)(abase[t] + aoff);
#pragma unroll
        for (int t = 0; t < 4; t++)
            pv[t] = *(const float4*)(bbase + (size_t)(bk + t * 8) * 512);
#pragma unroll
        for (int t = 0; t < 4; t++) *(float4*)&As[0][awoff + t * 1024] = cvt4(pa[t]);
#pragma unroll
        for (int t = 0; t < 4; t++) *(float4*)&Bs[0][bwoff + t * 8 * 136] = cvt4(pv[t]);
    }
    __syncthreads();

    int bsel = 0;
    for (int it = 0; it < 1024; it++) {
        if (it < 1023) {
            int k0 = (it + 1) * 32;
            int k = k0 + aq * 4;
            int cc = k >> 8, rem = k & 255;
            const size_t aoff = (size_t)cc * 262144 + (rem >> 4) * 512 + (rem & 15);
#pragma unroll
            for (int t = 0; t < 4; t++) pa[t] = *(const float4*)(abase[t] + aoff);
#pragma unroll
            for (int t = 0; t < 4; t++)
                pv[t] = *(const float4*)(bbase + (size_t)(k0 + bk + t * 8) * 512);
        }

        const float* Asb = As[bsel];
        const float* Bsb = Bs[bsel];
#pragma unroll
        for (int kk = 0; kk < 4; kk++) {
            uint32_t af[2][4], bf[8][2];
            const int kq0 = kk * 2, kq1 = kk * 2 + 1;
            const int kb  = lane & 3;
#pragma unroll
            for (int ma = 0; ma < 2; ma++) {
                int r0 = warp_m + ma * 16 + (lane >> 2);
                int r1 = r0 + 8;
                af[ma][0] = ldu(&Asb[r0 * 32 + ((kq0 ^ (r0 & 7)) << 2) + kb]);
                af[ma][1] = ldu(&Asb[r1 * 32 + ((kq0 ^ (r1 & 7)) << 2) + kb]);
                af[ma][2] = ldu(&Asb[r0 * 32 + ((kq1 ^ (r0 & 7)) << 2) + kb]);
                af[ma][3] = ldu(&Asb[r1 * 32 + ((kq1 ^ (r1 & 7)) << 2) + kb]);
            }
#pragma unroll
            for (int na = 0; na < 8; na++) {
                int n = warp_n + na * 8 + (lane >> 2);
                bf[na][0] = ldu(&Bsb[(kk * 8 + kb) * 136 + n]);
                bf[na][1] = ldu(&Bsb[(kk * 8 + 4 + kb) * 136 + n]);
            }
#pragma unroll
            for (int ma = 0; ma < 2; ma++)
#pragma unroll
                for (int na = 0; na < 8; na++)
                    mma_tf32(c[ma][na], af[ma], bf[na]);
        }

        if (it < 1023) {
            int nb = bsel ^ 1;
#pragma unroll
            for (int t = 0; t < 4; t++) *(float4*)&As[nb][awoff + t * 1024] = cvt4(pa[t]);
#pragma unroll
            for (int t = 0; t < 4; t++) *(float4*)&Bs[nb][bwoff + t * 8 * 136] = cvt4(pv[t]);
            __syncthreads();
            bsel = nb;
        }
    }

#pragma unroll
    for (int ma = 0; ma < 2; ma++) {
        int r0 = m0 + warp_m + ma * 16 + (lane >> 2);
        int r1 = r0 + 8;
        int tok0 = r0 & 1023, tok1 = r1 & 1023;
#pragma unroll
        for (int na = 0; na < 8; na++) {
            int col = n0 + warp_n + na * 8 + (lane & 3) * 2;
            float2 o0, o1;
            o0.x = c[ma][na][0] + pb[col]     + pos[(size_t)tok0 * 512 + col];
            o0.y = c[ma][na][1] + pb[col + 1] + pos[(size_t)tok0 * 512 + col + 1];
            o1.x = c[ma][na][2] + pb[col]     + pos[(size_t)tok1 * 512 + col];
            o1.y = c[ma][na][3] + pb[col + 1] + pos[(size_t)tok1 * 512 + col + 1];
            *(float2*)(g_x + (size_t)r0 * 512 + col) = o0;
            *(float2*)(g_x + (size_t)r1 * 512 + col) = o1;
        }
    }
}

// ============================================================================
// generic TC GEMM (TF32):  C[M][N] = A[M][K] @ B[K][N]  (+bias)(+gelu)(+resid g_x)
// CTA tile 128 x BN, BK=32, 8 warps (warp 32m x BN/2 n), double-buffered.
// Batched over blockIdx.z with separate batch/head strides (z = bb*hc + hd).
// ============================================================================
template<int BN>
__global__ __launch_bounds__(256, 1)
void k_tc_nn(int aId, unsigned long long aBatch, unsigned long long aHead, int ldA,
             const float* __restrict__ Bext, int bId,
             unsigned long long bBatch, unsigned long long bHead,
             unsigned long long bOff, int ldB,
             int cId, unsigned long long cBatch, unsigned long long cHead,
             unsigned long long cOff, int ldC,
             int K, int hc,
             const float* __restrict__ bias, int addResid, int gelu) {
    constexpr int BPAD = BN + 8;
    constexpr int NA = BN / 16;          // n atoms per warp
    constexpr int BCHUNKS = BN / 4;      // float4 chunks per B row
    constexpr int BROWS_PASS = 1024 / BN;// B rows loaded per pass
    constexpr int BPASS = BN / 32;       // passes to cover 32 rows

    __shared__ __align__(16) float As[2][128 * 32];
    __shared__ __align__(16) float Bs[2][32 * BPAD];

    const int tid  = threadIdx.x;
    const int lane = tid & 31;
    const int wid  = tid >> 5;
    const int warp_m = (wid & 3) * 32;
    const int warp_n = (wid >> 2) * (BN / 2);
    const int m0 = blockIdx.y * 128;
    const int n0 = blockIdx.x * BN;

    const int z  = blockIdx.z;
    const int bb = z / hc;
    const int hd = z % hc;
    const float* A = buf(aId) + (size_t)bb * aBatch + (size_t)hd * aHead;
    const float* Bg = (bId < 0 ? Bext : buf(bId)) +
                      (size_t)bb * bBatch + (size_t)hd * bHead + bOff;
    float* C = buf(cId) + (size_t)bb * cBatch + (size_t)hd * cHead + cOff;

    const int aq = tid & 7;
    const int am = tid >> 3;
    const int bc = tid % BCHUNKS;
    const int bk = tid / BCHUNKS;

    const int awoff = am * 32 + ((aq ^ (am & 7)) << 2);
    const int bwoff = bk * BPAD + bc * 4;

    float c[2][NA][4];
#pragma unroll
    for (int i = 0; i < 2; i++)
#pragma unroll
        for (int j = 0; j < NA; j++)
#pragma unroll
            for (int q = 0; q < 4; q++) c[i][j][q] = 0.0f;

    float4 pa[4], pv[BPASS];

    {
#pragma unroll
        for (int t = 0; t < 4; t++)
            pa[t] = *(const float4*)(A + (size_t)(m0 + am + t * 32) * ldA + aq * 4);
#pragma unroll
        for (int t = 0; t < BPASS; t++)
            pv[t] = *(const float4*)(Bg + (size_t)(bk + t * BROWS_PASS) * ldB + n0 + bc * 4);
#pragma unroll
        for (int t = 0; t < 4; t++) *(float4*)&As[0][awoff + t * 1024] = cvt4(pa[t]);
#pragma unroll
        for (int t = 0; t < BPASS; t++)
            *(float4*)&Bs[0][bwoff + t * BROWS_PASS * BPAD] = cvt4(pv[t]);
    }
    __syncthreads();

    const int iters = K >> 5;
    int bsel = 0;
    for (int it = 0; it < iters; it++) {
        if (it < iters - 1) {
            int k0 = (it + 1) * 32;
#pragma unroll
            for (int t = 0; t < 4; t++)
                pa[t] = *(const float4*)(A + (size_t)(m0 + am + t * 32) * ldA + k0 + aq * 4);
#pragma unroll
            for (int t = 0; t < BPASS; t++)
                pv[t] = *(const float4*)(Bg + (size_t)(k0 + bk + t * BROWS_PASS) * ldB + n0 + bc * 4);
        }

        const float* Asb = As[bsel];
        const float* Bsb = Bs[bsel];
#pragma unroll
        for (int kk = 0; kk < 4; kk++) {
            uint32_t af[2][4], bf[NA][2];
            const int kq0 = kk * 2, kq1 = kk * 2 + 1;
            const int kb  = lane & 3;
#pragma unroll
            for (int ma = 0; ma < 2; ma++) {
                int r0 = warp_m + ma * 16 + (lane >> 2);
                int r1 = r0 + 8;
                af[ma][0] = ldu(&Asb[r0 * 32 + ((kq0 ^ (r0 & 7)) << 2) + kb]);
                af[ma][1] = ldu(&Asb[r1 * 32 + ((kq0 ^ (r1 & 7)) << 2) + kb]);
                af[ma][2] = ldu(&Asb[r0 * 32 + ((kq1 ^ (r0 & 7)) << 2) + kb]);
                af[ma][3] = ldu(&Asb[r1 * 32 + ((kq1 ^ (r1 & 7)) << 2) + kb]);
            }
#pragma unroll
            for (int na = 0; na < NA; na++) {
                int n = warp_n + na * 8 + (lane >> 2);
                bf[na][0] = ldu(&Bsb[(kk * 8 + kb) * BPAD + n]);
                bf[na][1] = ldu(&Bsb[(kk * 8 + 4 + kb) * BPAD + n]);
            }
#pragma unroll
            for (int ma = 0; ma < 2; ma++)
#pragma unroll
                for (int na = 0; na < NA; na++)
                    mma_tf32(c[ma][na], af[ma], bf[na]);
        }

        if (it < iters - 1) {
            int nb = bsel ^ 1;
#pragma unroll
            for (int t = 0; t < 4; t++) *(float4*)&As[nb][awoff + t * 1024] = cvt4(pa[t]);
#pragma unroll
            for (int t = 0; t < BPASS; t++)
                *(float4*)&Bs[nb][bwoff + t * BROWS_PASS * BPAD] = cvt4(pv[t]);
            __syncthreads();
            bsel = nb;
        }
    }

    // epilogue
#pragma unroll
    for (int ma = 0; ma < 2; ma++) {
        int r0 = m0 + warp_m + ma * 16 + (lane >> 2);
        int r1 = r0 + 8;
#pragma unroll
        for (int na = 0; na < NA; na++) {
            int col = n0 + warp_n + na * 8 + (lane & 3) * 2;
            float v[4] = {c[ma][na][0], c[ma][na][1], c[ma][na][2], c[ma][na][3]};
            if (bias) {
                float b0 = bias[col], b1 = bias[col + 1];
                v[0] += b0; v[1] += b1; v[2] += b0; v[3] += b1;
            }
            if (gelu) {
#pragma unroll
                for (int q = 0; q < 4; q++)
                    v[q] = 0.5f * v[q] * (1.0f + erff(v[q] * 0.70710678118654752f));
            }
            if (addResid) {
                v[0] += g_x[(size_t)r0 * 512 + col];
                v[1] += g_x[(size_t)r0 * 512 + col + 1];
                v[2] += g_x[(size_t)r1 * 512 + col];
                v[3] += g_x[(size_t)r1 * 512 + col + 1];
            }
            *(float2*)(C + (size_t)r0 * ldC + col) = make_float2(v[0], v[1]);
            *(float2*)(C + (size_t)r1 * ldC + col) = make_float2(v[2], v[3]);
        }
    }
}

// ============================================================================
// attention scores (TC, TF32, K=64 single shot):
//   S[z][i][j] = (Q_i . K_j)/8 + tbl[relidx(i,j)][head]
// CTA 128i x 128j, 8 warps.
// ============================================================================
__global__ __launch_bounds__(256, 1)
void k_tc_scores(const float* __restrict__ tbl, int qkvld, int inner, int hc) {
    __shared__ __align__(16) float As[128 * 64];   // Q tile, swizzled
    __shared__ __align__(16) float Bs[64 * 136];   // K^T tile [k][j]

    const int tid  = threadIdx.x;
    const int lane = tid & 31;
    const int wid  = tid >> 5;
    const int warp_m = (wid & 3) * 32;
    const int warp_n = (wid >> 2) * 64;
    const int i0 = blockIdx.y * 128;
    const int j0 = blockIdx.x * 128;

    const int z = blockIdx.z;
    const int bb = z / hc, head = z % hc;
    const float* Qb = g_qkv + (size_t)bb * 1024 * qkvld + head * 64;
    const float* Kb = Qb + inner;

    // load Q tile: am=tid>>4 (16 rows/pass), aq=tid&15 (k-chunk)
    {
        const int aq = tid & 15;
        const int am = tid >> 4;
#pragma unroll
        for (int t = 0; t < 8; t++) {
            int m = am + t * 16;
            float4 v = *(const float4*)(Qb + (size_t)(i0 + m) * qkvld + aq * 4);
            int p = (aq & 8) | ((aq ^ (m & 7)) & 7);
            *(float4*)&As[m * 64 + (p << 2)] = cvt4(v);
        }
    }
    // load K tile transposed: n=tid&127, c=tid>>7; kq = c + t*2 (16 quads)
    {
        const int n = tid & 127;
        const int cc = tid >> 7;
#pragma unroll
        for (int t = 0; t < 8; t++) {
            int kq = cc + t * 2;
            float4 v = cvt4(*(const float4*)(Kb + (size_t)(j0 + n) * qkvld + kq * 4));
            Bs[(kq * 4 + 0) * 136 + n] = v.x;
            Bs[(kq * 4 + 1) * 136 + n] = v.y;
            Bs[(kq * 4 + 2) * 136 + n] = v.z;
            Bs[(kq * 4 + 3) * 136 + n] = v.w;
        }
    }
    __syncthreads();

    float c[2][8][4];
#pragma unroll
    for (int i = 0; i < 2; i++)
#pragma unroll
        for (int j = 0; j < 8; j++)
#pragma unroll
            for (int q = 0; q < 4; q++) c[i][j][q] = 0.0f;

#pragma unroll
    for (int kk = 0; kk < 8; kk++) {
        uint32_t af[2][4], bf[8][2];
        const int kq0 = kk * 2, kq1 = kk * 2 + 1;
        const int kb  = lane & 3;
#pragma unroll
        for (int ma = 0; ma < 2; ma++) {
            int r0 = warp_m + ma * 16 + (lane >> 2);
            int r1 = r0 + 8;
            int p00 = (kq0 & 8) | ((kq0 ^ (r0 & 7)) & 7);
            int p01 = (kq0 & 8) | ((kq0 ^ (r1 & 7)) & 7);
            int p10 = (kq1 & 8) | ((kq1 ^ (r0 & 7)) & 7);
            int p11 = (kq1 & 8) | ((kq1 ^ (r1 & 7)) & 7);
            af[ma][0] = ldu(&As[r0 * 64 + (p00 << 2) + kb]);
            af[ma][1] = ldu(&As[r1 * 64 + (p01 << 2) + kb]);
            af[ma][2] = ldu(&As[r0 * 64 + (p10 << 2) + kb]);
            af[ma][3] = ldu(&As[r1 * 64 + (p11 << 2) + kb]);
        }
#pragma unroll
        for (int na = 0; na < 8; na++) {
            int n = warp_n + na * 8 + (lane >> 2);
            bf[na][0] = ldu(&Bs[(kk * 8 + kb) * 136 + n]);
            bf[na][1] = ldu(&Bs[(kk * 8 + 4 + kb) * 136 + n]);
        }
#pragma unroll
        for (int ma = 0; ma < 2; ma++)
#pragma unroll
            for (int na = 0; na < 8; na++)
                mma_tf32(c[ma][na], af[ma], bf[na]);
    }

    float* Sp = g_attn + (size_t)z * 1048576;
#pragma unroll
    for (int ma = 0; ma < 2; ma++) {
        int r0 = i0 + warp_m + ma * 16 + (lane >> 2);
        int r1 = r0 + 8;
        int ih0 = r0 >> 5, iw0 = r0 & 31;
        int ih1 = r1 >> 5, iw1 = r1 & 31;
#pragma unroll
        for (int na = 0; na < 8; na++) {
            int jj = j0 + warp_n + na * 8 + (lane & 3) * 2;
            int jh0 = jj >> 5, jw0 = jj & 31;
            int jh1 = (jj + 1) >> 5, jw1 = (jj + 1) & 31;
            float2 o0, o1;
            o0.x = c[ma][na][0] * 0.125f +
                   tbl[(size_t)((ih0 - jh0 + 31) * 63 + (iw0 - jw0 + 31)) * hc + head];
            o0.y = c[ma][na][1] * 0.125f +
                   tbl[(size_t)((ih0 - jh1 + 31) * 63 + (iw0 - jw1 + 31)) * hc + head];
            o1.x = c[ma][na][2] * 0.125f +
                   tbl[(size_t)((ih1 - jh0 + 31) * 63 + (iw1 - jw0 + 31)) * hc + head];
            o1.y = c[ma][na][3] * 0.125f +
                   tbl[(size_t)((ih1 - jh1 + 31) * 63 + (iw1 - jw1 + 31)) * hc + head];
            *(float2*)(Sp + (size_t)r0 * 1024 + jj) = o0;
            *(float2*)(Sp + (size_t)r1 * 1024 + jj) = o1;
        }
    }
}

// ============================================================================
// row softmax over 1024 columns (one block = one row)
// ============================================================================
__global__ void k_softmax() {
    __shared__ float sh[8];
    int tid = threadIdx.x;
    float* row = g_attn + (size_t)blockIdx.x * 1024;
    float4 v = ((float4*)row)[tid];
    float m = fmaxf(fmaxf(v.x, v.y), fmaxf(v.z, v.w));
#pragma unroll
    for (int o = 16; o; o >>= 1) m = fmaxf(m, __shfl_xor_sync(0xffffffffu, m, o));
    if ((tid & 31) == 0) sh[tid >> 5] = m;
    __syncthreads();
    float m8 = sh[0];
#pragma unroll
    for (int i = 1; i < 8; i++) m8 = fmaxf(m8, sh[i]);
    float4 e;
    e.x = __expf(v.x - m8); e.y = __expf(v.y - m8);
    e.z = __expf(v.z - m8); e.w = __expf(v.w - m8);
    float s = e.x + e.y + e.z + e.w;
#pragma unroll
    for (int o = 16; o; o >>= 1) s += __shfl_xor_sync(0xffffffffu, s, o);
    __syncthreads();
    if ((tid & 31) == 0) sh[tid >> 5] = s;
    __syncthreads();
    float tot = 0.f;
#pragma unroll
    for (int i = 0; i < 8; i++) tot += sh[i];
    float inv = 1.0f / tot;
    e.x *= inv; e.y *= inv; e.z *= inv; e.w *= inv;
    ((float4*)row)[tid] = e;
}

// ============================================================================
// LayerNorm over 512 (one block per row): reads g_x, writes g_xn
// ============================================================================
__global__ void k_layernorm(const float* __restrict__ s, const float* __restrict__ b) {
    __shared__ float ssum[4], ssq[4];
    int tid = threadIdx.x;
    int row = blockIdx.x;
    float4 v = ((const float4*)(g_x + (size_t)row * 512))[tid];
    float sum = v.x + v.y + v.z + v.w;
    float sq  = v.x * v.x + v.y * v.y + v.z * v.z + v.w * v.w;
#pragma unroll
    for (int o = 16; o; o >>= 1) {
        sum += __shfl_xor_sync(0xffffffffu, sum, o);
        sq  += __shfl_xor_sync(0xffffffffu, sq, o);
    }
    if ((tid & 31) == 0) { ssum[tid >> 5] = sum; ssq[tid >> 5] = sq; }
    __syncthreads();
    float ts = ssum[0] + ssum[1] + ssum[2] + ssum[3];
    float tq = ssq[0] + ssq[1] + ssq[2] + ssq[3];
    float mean = ts * (1.0f / 512.0f);
    float var  = tq * (1.0f / 512.0f) - mean * mean;
    float rstd = rsqrtf(var + 1e-5f);
    int d = tid << 2;
    float4 sv = *(const float4*)(s + d);
    float4 bv = *(const float4*)(b + d);
    float4 o;
    o.x = (v.x - mean) * rstd * sv.x + bv.x;
    o.y = (v.y - mean) * rstd * sv.y + bv.y;
    o.z = (v.z - mean) * rstd * sv.z + bv.z;
    o.w = (v.w - mean) * rstd * sv.w + bv.w;
    ((float4*)(g_xn + (size_t)row * 512))[tid] = o;
}

// ============================================================================
// final layout: out[b][d][n] = g_x[b][n][d]
// ============================================================================
__global__ void k_out(float* __restrict__ out) {
    __shared__ float t[32][33];
    int bb = blockIdx.z;
    int n0 = blockIdx.x * 32, d0 = blockIdx.y * 32;
    int tx = threadIdx.x, ty = threadIdx.y;   // 32 x 8
#pragma unroll
    for (int i = 0; i < 32; i += 8)
        t[ty + i][tx] = g_x[((size_t)bb * 1024 + n0 + ty + i) * 512 + d0 + tx];
    __syncthreads();
#pragma unroll
    for (int i = 0; i < 32; i += 8)
        out[((size_t)bb * 512 + d0 + ty + i) * 1024 + n0 + tx] = t[tx][ty + i];
}

// ============================================================================
// host orchestration
// ============================================================================
extern "C" void kernel_launch(void* const* d_in, const int* in_sizes, int n_in,
                              void* d_out, int out_size) {
    const float *img = 0, *patch_w = 0, *patch_b = 0, *pos_emb = 0;
    const float *ln1_s = 0, *ln1_b = 0, *ln2_s = 0, *ln2_b = 0;
    const float *qkv_w[3] = {0, 0, 0}, *out_w[3] = {0, 0, 0}, *out_b[3] = {0, 0, 0};
    const float *tbl[3] = {0, 0, 0};
    const float *ff_w1 = 0, *ff_b1 = 0, *ff_w2 = 0, *ff_b2 = 0;
    int c512 = 0, c1536 = 0, c393 = 0;
    for (int i = 0; i < n_in; i++) {
        const float* p = (const float*)d_in[i];
        switch (in_sizes[i]) {
            case 134217728: img = p; break;
            case 16777216: patch_w = p; break;
            case 524288:   pos_emb = p; break;
            case 512: {
                const float** t[4] = {&patch_b, &out_b[0], &out_b[1], &out_b[2]};
                if (c512 < 4) *t[c512] = p;
                c512++;
            } break;
            case 1536: {
                const float** t[5] = {&ln1_s, &ln1_b, &ln2_s, &ln2_b, &ff_b2};
                if (c1536 < 5) *t[c1536] = p;
                c1536++;
            } break;
            case 768:    ff_b1 = p; break;
            case 196608: qkv_w[0] = p; break;
            case 393216: {
                const float** t[3] = {&qkv_w[1], &ff_w1, &ff_w2};
                if (c393 < 3) *t[c393] = p;
                c393++;
            } break;
            case 786432: qkv_w[2] = p; break;
            case 65536:  out_w[0] = p; break;
            case 131072: out_w[1] = p; break;
            case 262144: out_w[2] = p; break;
            case 7938:   tbl[0] = p; break;
            case 15876:  tbl[1] = p; break;
            case 31752:  tbl[2] = p; break;
            default: break;
        }
    }

    bool ok = img && patch_w && patch_b && pos_emb && ln1_s && ln1_b && ln2_s &&
              ln2_b && ff_w1 && ff_b1 && ff_w2 && ff_b2;
    for (int l = 0; l < 3; l++)
        ok = ok && qkv_w[l] && out_w[l] && out_b[l] && tbl[l];
    if (!ok) {
        k_zero<<<(out_size + 255) / 256, 256>>>((float*)d_out, out_size);
        return;
    }

    k_permute_pw<<<(32768 * 128 + 255) / 256, 256>>>(patch_w);
    k_patch_tc<<<dim3(4, 32), 256>>>(img, patch_b, pos_emb);

    const int heads[3] = {2, 4, 8};
    for (int l = 0; l < 3; l++) {
        int h = heads[l];
        int inner = 64 * h;
        int qkvld = 3 * inner;

        // ---- attention ----
        k_layernorm<<<4096, 128>>>(ln1_s + l * 512, ln1_b + l * 512);
        // QKV = xn @ qkv_w   [4096 x qkvld]
        k_tc_nn<128><<<dim3(qkvld / 128, 32, 1), 256>>>(
            BUF_XN, 0ULL, 0ULL, 512,
            qkv_w[l], -1, 0ULL, 0ULL, 0ULL, qkvld,
            BUF_QKV, 0ULL, 0ULL, 0ULL, qkvld,
            512, 1, nullptr, 0, 0);
        // S = Q K^T / 8 + rel
        k_tc_scores<<<dim3(8, 8, 4 * h), 256>>>(tbl[l], qkvld, inner, h);
        k_softmax<<<4 * h * 1024, 256>>>();
        // O_head = S @ V  (per z, N=64)
        k_tc_nn<64><<<dim3(1, 8, 4 * h), 256>>>(
            BUF_ATT, (unsigned long long)h * 1048576ULL, 1048576ULL, 1024,
            nullptr, BUF_QKV, (unsigned long long)1024 * qkvld, 64ULL,
            (unsigned long long)(2 * inner), qkvld,
            BUF_O, (unsigned long long)1024 * inner, 64ULL, 0ULL, inner,
            1024, h, nullptr, 0, 0);
        // x += O @ out_w + out_b
        k_tc_nn<128><<<dim3(4, 32, 1), 256>>>(
            BUF_O, 0ULL, 0ULL, inner,
            out_w[l], -1, 0ULL, 0ULL, 0ULL, 512,
            BUF_X, 0ULL, 0ULL, 0ULL, 512,
            inner, 1, out_b[l], 1, 0);

        // ---- feed-forward ----
        k_layernorm<<<4096, 128>>>(ln2_s + l * 512, ln2_b + l * 512);
        k_tc_nn<128><<<dim3(2, 32, 1), 256>>>(
            BUF_XN, 0ULL, 0ULL, 512,
            ff_w1 + (size_t)l * 512 * 256, -1, 0ULL, 0ULL, 0ULL, 256,
            BUF_H, 0ULL, 0ULL, 0ULL, 256,
            512, 1, ff_b1 + l * 256, 0, 1);
        k_tc_nn<128><<<dim3(4, 32, 1), 256>>>(
            BUF_H, 0ULL, 0ULL, 256,
            ff_w2 + (size_t)l * 256 * 512, -1, 0ULL, 0ULL, 0ULL, 512,
            BUF_X, 0ULL, 0ULL, 0ULL, 512,
            256, 1, ff_b2 + l * 512, 1, 0);
    }

    k_out<<<dim3(32, 16, 4), dim3(32, 8)>>>((float*)d_out);
}